// round 4
// baseline (speedup 1.0000x reference)
#include <cuda_runtime.h>
#include <cuda_bf16.h>
#include <math.h>
#include <stdint.h>

#define SEQ   1024
#define EMB   2880
#define NH    64
#define NKV   8
#define HDIM  64
#define HD    4096
#define KVD   512
#define WIN   128
#define QT    8
#define NKEY  135
#define KSTR  68
#define NPAD  2944   // Wo rows padded to 23*128

// ---------------- device-global scratch ----------------
__device__ __align__(256) float g_q[SEQ*HD];
__device__ __align__(256) float g_k[SEQ*KVD];
__device__ __align__(256) float g_v[SEQ*KVD];
__device__ __align__(256) __nv_bfloat16 g_xhi[SEQ*EMB],  g_xlo[SEQ*EMB];
__device__ __align__(256) __nv_bfloat16 g_ahi[SEQ*HD],   g_alo[SEQ*HD];
__device__ __align__(256) __nv_bfloat16 g_Wqhi[HD*EMB],  g_Wqlo[HD*EMB];
__device__ __align__(256) __nv_bfloat16 g_Wkhi[KVD*EMB], g_Wklo[KVD*EMB];
__device__ __align__(256) __nv_bfloat16 g_Wvhi[KVD*EMB], g_Wvlo[KVD*EMB];
__device__ __align__(256) __nv_bfloat16 g_Wohi[NPAD*HD], g_Wolo[NPAD*HD];

// ---------------- helpers ----------------
__device__ __forceinline__ uint32_t smem_u32(const void* p) {
    uint32_t a;
    asm("{ .reg .u64 t; cvta.to.shared.u64 t, %1; cvt.u32.u64 %0, t; }"
        : "=r"(a) : "l"(p));
    return a;
}

#define LDSM4(d, addr) \
    asm volatile("ldmatrix.sync.aligned.m8n8.x4.shared.b16 {%0,%1,%2,%3}, [%4];" \
        : "=r"((d)[0]), "=r"((d)[1]), "=r"((d)[2]), "=r"((d)[3]) : "r"(addr))

#define MMA16816(d, a, b0, b1) \
    asm volatile("mma.sync.aligned.m16n8k16.row.col.f32.bf16.bf16.f32 " \
        "{%0,%1,%2,%3}, {%4,%5,%6,%7}, {%8,%9}, {%0,%1,%2,%3};" \
        : "+f"((d)[0]), "+f"((d)[1]), "+f"((d)[2]), "+f"((d)[3]) \
        : "r"((a)[0]), "r"((a)[1]), "r"((a)[2]), "r"((a)[3]), "r"(b0), "r"(b1))

#define CP16(dst, src) \
    asm volatile("cp.async.cg.shared.global [%0], [%1], 16;" \
        :: "r"(dst), "l"((const void*)(src)) : "memory")
#define CP_COMMIT() asm volatile("cp.async.commit_group;" ::: "memory")
#define CP_WAIT1()  asm volatile("cp.async.wait_group 1;" ::: "memory")

// ---------------- split pre-pass: fp32 -> bf16 hi + bf16 lo ----------------
__global__ void split_kernel(const float* __restrict__ src,
                             __nv_bfloat16* __restrict__ hi,
                             __nv_bfloat16* __restrict__ lo,
                             int n_src, int n_tot) {
    int i = (blockIdx.x * blockDim.x + threadIdx.x) * 4;
    if (i >= n_tot) return;
    float4 v = (i < n_src) ? *(const float4*)(src + i)
                           : make_float4(0.f, 0.f, 0.f, 0.f);
    __nv_bfloat162 h01 = __floats2bfloat162_rn(v.x, v.y);
    __nv_bfloat162 h23 = __floats2bfloat162_rn(v.z, v.w);
    __nv_bfloat162 l01 = __floats2bfloat162_rn(v.x - __bfloat162float(h01.x),
                                               v.y - __bfloat162float(h01.y));
    __nv_bfloat162 l23 = __floats2bfloat162_rn(v.z - __bfloat162float(h23.x),
                                               v.w - __bfloat162float(h23.y));
    uint2 H = make_uint2(*(uint32_t*)&h01, *(uint32_t*)&h23);
    uint2 L = make_uint2(*(uint32_t*)&l01, *(uint32_t*)&l23);
    *(uint2*)(hi + i) = H;
    *(uint2*)(lo + i) = L;
}

// ---------------- split-bf16 HMMA GEMM (pre-split operands) ----------------
// C[128 x nvalid] = A[128,K] @ B[128,K]^T + bias. BM=BN=128, BK=32.
// 8 warps, warp tile 64x32, m16n8k16 x3 (AhBh + AlBh + AhBl).
#define GKC 32
#define ASTR 40
#define REG_BYTES (128*ASTR*2)        // 10240
#define STAGE_BYTES (4*REG_BYTES)     // 40960 (Ahi Alo Bhi Blo)
#define GSMEM (2*STAGE_BYTES + 512)   // 82432

__device__ __forceinline__ void gemm_core(
        const __nv_bfloat16* __restrict__ Ahi, const __nv_bfloat16* __restrict__ Alo, int lda,
        const __nv_bfloat16* __restrict__ Bhi, const __nv_bfloat16* __restrict__ Blo, int ldb,
        const float* __restrict__ bias, int nvalid,
        float* __restrict__ C, int ldc, int K) {
    extern __shared__ char smem[];
    uint32_t sb = smem_u32(smem);
    float* bias_sh = (float*)(smem + 2 * STAGE_BYTES);

    int tid  = threadIdx.x;
    int lane = tid & 31;
    int w    = tid >> 5;
    int bm   = blockIdx.y * 128;
    int wm   = (w >> 2) * 64;
    int wn   = (w & 3) * 32;

    if (tid < 128) bias_sh[tid] = (tid < nvalid) ? bias[tid] : 0.0f;

    const __nv_bfloat16* pA0 = Ahi + (size_t)bm * lda;
    const __nv_bfloat16* pA1 = Alo + (size_t)bm * lda;

    // cp.async per-thread coords: 8 chunks of 16B
    int row = tid >> 2, c4 = tid & 3;

#define LOAD_STAGE(soff, kt) do {                                               \
    uint32_t d = sb + (soff) + (uint32_t)(row * 80 + c4 * 16);                  \
    size_t sa = (size_t)row * lda + (kt) + c4 * 8;                              \
    size_t sa2 = sa + (size_t)64 * lda;                                         \
    size_t sbb = (size_t)row * ldb + (kt) + c4 * 8;                             \
    size_t sbb2 = sbb + (size_t)64 * ldb;                                       \
    CP16(d,                        pA0 + sa);                                   \
    CP16(d + 5120,                 pA0 + sa2);                                  \
    CP16(d + REG_BYTES,            pA1 + sa);                                   \
    CP16(d + REG_BYTES + 5120,     pA1 + sa2);                                  \
    CP16(d + 2*REG_BYTES,          Bhi + sbb);                                  \
    CP16(d + 2*REG_BYTES + 5120,   Bhi + sbb2);                                 \
    CP16(d + 3*REG_BYTES,          Blo + sbb);                                  \
    CP16(d + 3*REG_BYTES + 5120,   Blo + sbb2);                                 \
} while (0)

    // ldmatrix per-lane offsets (bytes)
    int r = lane & 7, g = lane >> 3;
    uint32_t aoff = (uint32_t)(((wm + ((g & 1) << 3) + r) * ASTR + ((g >> 1) << 3)) * 2);
    uint32_t boff = (uint32_t)(((wn + (((g >> 1) & 1) << 3) + r) * ASTR + ((g & 1) << 3)) * 2);

    float acc[4][4][4];
#pragma unroll
    for (int i = 0; i < 4; i++)
#pragma unroll
        for (int j = 0; j < 4; j++)
#pragma unroll
            for (int q = 0; q < 4; q++) acc[i][j][q] = 0.0f;

    int NC = K / GKC;
    LOAD_STAGE(0, 0);            CP_COMMIT();
    LOAD_STAGE(STAGE_BYTES, GKC); CP_COMMIT();

    for (int c = 0; c < NC; c++) {
        CP_WAIT1();
        __syncthreads();
        uint32_t buf = sb + (uint32_t)((c & 1) * STAGE_BYTES);
#pragma unroll
        for (int ks = 0; ks < 2; ks++) {
            uint32_t kb = (uint32_t)(ks * 32);
            uint32_t bH[2][4], bL[2][4];
#pragma unroll
            for (int nf2 = 0; nf2 < 2; nf2++) {
                uint32_t bd = buf + 2 * REG_BYTES + boff + kb + (uint32_t)(nf2 * 16 * 80);
                LDSM4(bH[nf2], bd);
                LDSM4(bL[nf2], bd + REG_BYTES);
            }
#pragma unroll
            for (int mf = 0; mf < 4; mf++) {
                uint32_t aH[4], aL[4];
                uint32_t ad = buf + aoff + kb + (uint32_t)(mf * 16 * 80);
                LDSM4(aH, ad);
                LDSM4(aL, ad + REG_BYTES);
#pragma unroll
                for (int nf = 0; nf < 4; nf++) {
                    uint32_t b0h = bH[nf >> 1][(nf & 1) * 2];
                    uint32_t b1h = bH[nf >> 1][(nf & 1) * 2 + 1];
                    uint32_t b0l = bL[nf >> 1][(nf & 1) * 2];
                    uint32_t b1l = bL[nf >> 1][(nf & 1) * 2 + 1];
                    MMA16816(acc[mf][nf], aH, b0h, b1h);
                    MMA16816(acc[mf][nf], aL, b0h, b1h);
                    MMA16816(acc[mf][nf], aH, b0l, b1l);
                }
            }
        }
        __syncthreads();
        if (c + 2 < NC) LOAD_STAGE((c & 1) * STAGE_BYTES, (c + 2) * GKC);
        CP_COMMIT();
    }
#undef LOAD_STAGE

    // epilogue
    int rr = lane >> 2, cc = (lane & 3) * 2;
#pragma unroll
    for (int mf = 0; mf < 4; mf++) {
        int row0 = bm + wm + mf * 16 + rr;
#pragma unroll
        for (int nf = 0; nf < 4; nf++) {
            int col = wn + nf * 8 + cc;
            if (col < nvalid) {
                float b0 = bias_sh[col], b1 = bias_sh[col + 1];
                float2 v0 = make_float2(acc[mf][nf][0] + b0, acc[mf][nf][1] + b1);
                float2 v1 = make_float2(acc[mf][nf][2] + b0, acc[mf][nf][3] + b1);
                *(float2*)(C + (size_t)row0 * ldc + col)       = v0;
                *(float2*)(C + (size_t)(row0 + 8) * ldc + col) = v1;
            }
        }
    }
}

// Fused QKV: n-tiles 0-31 -> Wq, 32-35 -> Wk, 36-39 -> Wv
__global__ void __launch_bounds__(256, 2)
qkv_gemm(const float* __restrict__ bq, const float* __restrict__ bk,
         const float* __restrict__ bv) {
    int nt = blockIdx.x;
    const __nv_bfloat16 *Bh, *Bl; const float* bi; float* C; int ldc;
    if (nt < 32) {
        Bh = g_Wqhi + (size_t)nt * 128 * EMB; Bl = g_Wqlo + (size_t)nt * 128 * EMB;
        bi = bq + nt * 128; C = g_q + nt * 128; ldc = HD;
    } else if (nt < 36) {
        int t = nt - 32;
        Bh = g_Wkhi + (size_t)t * 128 * EMB; Bl = g_Wklo + (size_t)t * 128 * EMB;
        bi = bk + t * 128; C = g_k + t * 128; ldc = KVD;
    } else {
        int t = nt - 36;
        Bh = g_Wvhi + (size_t)t * 128 * EMB; Bl = g_Wvlo + (size_t)t * 128 * EMB;
        bi = bv + t * 128; C = g_v + t * 128; ldc = KVD;
    }
    gemm_core(g_xhi, g_xlo, EMB, Bh, Bl, EMB, bi, 128, C, ldc, EMB);
}

__global__ void __launch_bounds__(256, 2)
oproj_gemm(const float* __restrict__ bo, float* __restrict__ out) {
    int n0 = blockIdx.x * 128;
    int nv = EMB - n0; if (nv > 128) nv = 128;
    gemm_core(g_ahi, g_alo, HD,
              g_Wohi + (size_t)n0 * HD, g_Wolo + (size_t)n0 * HD, HD,
              bo + n0, nv, out + n0, EMB, HD);
}

// ---------------- RoPE (YaRN) ----------------
__global__ void rope_kernel(const int* __restrict__ positions) {
    int s = blockIdx.x;
    int tid = threadIdx.x;
    __shared__ float csh[32], ssh[32];

    if (tid < 32) {
        float i2 = 2.0f * (float)tid;
        float pf = powf(150000.0f, i2 / 64.0f);
        double lbase = 2.0 * log(150000.0);
        double low  = 64.0 * log(4096.0 / (32.0 * 2.0 * M_PI)) / lbase;
        double high = 64.0 * log(4096.0 / (1.0  * 2.0 * M_PI)) / lbase;
        if (low  < 0.0)  low  = 0.0;
        if (high > 31.0) high = 31.0;
        float ramp = ((float)tid - (float)low) / (float)(high - low);
        ramp = fminf(fmaxf(ramp, 0.0f), 1.0f);
        float invf = (1.0f / (32.0f * pf)) * ramp + (1.0f / pf) * (1.0f - ramp);
        float mscale = 0.1f * logf(32.0f) + 1.0f;
        float ang = (float)positions[s] * invf;
        csh[tid] = cosf(ang) * mscale;
        ssh[tid] = sinf(ang) * mscale;
    }
    __syncthreads();

    for (int item = tid; item < (NH + NKV) * 32; item += blockDim.x) {
        int h = item >> 5;
        int i = item & 31;
        float* base = (h < NH) ? (g_q + (size_t)s * HD + h * HDIM)
                               : (g_k + (size_t)s * KVD + (h - NH) * HDIM);
        float x0 = base[i];
        float x1 = base[i + 32];
        base[i]      = x0 * csh[i] - x1 * ssh[i];
        base[i + 32] = x1 * csh[i] + x0 * ssh[i];
    }
}

// ---------------- Attention (writes bf16 hi/lo directly) ----------------
__global__ void attn_kernel(const float* __restrict__ sinks) {
    extern __shared__ float asmem[];
    float* k_sh = asmem;
    float* v_sh = k_sh + NKEY * KSTR;
    float* q_sh = v_sh + NKEY * KSTR;
    float* p_sh = q_sh + QT * 512;

    int kvh  = blockIdx.x;
    int q0   = blockIdx.y * QT;
    int base = q0 - (WIN - 1);
    int tid  = threadIdx.x;
    int w    = tid >> 5;
    int lane = tid & 31;

    for (int i4 = tid; i4 < NKEY * 16; i4 += 256) {
        int row = i4 >> 4, d4 = i4 & 15;
        int sg = base + row;
        float4 kv = make_float4(0.f, 0.f, 0.f, 0.f);
        float4 vv = make_float4(0.f, 0.f, 0.f, 0.f);
        if (sg >= 0) {
            kv = *(const float4*)(g_k + (size_t)sg * KVD + kvh * HDIM + d4 * 4);
            vv = *(const float4*)(g_v + (size_t)sg * KVD + kvh * HDIM + d4 * 4);
        }
        *(float4*)(k_sh + row * KSTR + d4 * 4) = kv;
        *(float4*)(v_sh + row * KSTR + d4 * 4) = vv;
    }
    for (int i4 = tid; i4 < QT * 128; i4 += 256) {
        int j = i4 >> 7, d4 = i4 & 127;
        *(float4*)(q_sh + j * 512 + d4 * 4) =
            *(const float4*)(g_q + (size_t)(q0 + j) * HD + kvh * 512 + d4 * 4);
    }
    __syncthreads();

    int h = kvh * 8 + w;
    float sinkv = sinks[h];

    for (int j = 0; j < QT; j++) {
        float4 qr[16];
        const float4* q4 = (const float4*)(q_sh + j * 512 + w * 64);
#pragma unroll
        for (int d = 0; d < 16; d++) qr[d] = q4[d];

        float sc[4];
        bool  val[4];
        float mx = -INFINITY;
#pragma unroll
        for (int m = 0; m < 4; m++) {
            int off = j + lane + 32 * m;
            int sg  = base + off;
            val[m] = (sg >= 0);
            const float4* k4 = (const float4*)(k_sh + off * KSTR);
            float acc = 0.0f;
#pragma unroll
            for (int d = 0; d < 16; d++) {
                float4 kv = k4[d];
                acc += qr[d].x * kv.x + qr[d].y * kv.y
                     + qr[d].z * kv.z + qr[d].w * kv.w;
            }
            sc[m] = acc * 0.125f;
            if (val[m]) mx = fmaxf(mx, sc[m]);
        }
#pragma unroll
        for (int o = 16; o; o >>= 1) mx = fmaxf(mx, __shfl_xor_sync(0xFFFFFFFFu, mx, o));
        mx = fmaxf(mx, sinkv);

        float lsum = 0.0f;
        float p[4];
#pragma unroll
        for (int m = 0; m < 4; m++) {
            p[m] = val[m] ? __expf(sc[m] - mx) : 0.0f;
            lsum += p[m];
        }
#pragma unroll
        for (int o = 16; o; o >>= 1) lsum += __shfl_xor_sync(0xFFFFFFFFu, lsum, o);
        float inv = 1.0f / (lsum + __expf(sinkv - mx));

#pragma unroll
        for (int m = 0; m < 4; m++)
            p_sh[w * WIN + lane + 32 * m] = p[m] * inv;
        __syncwarp();

        float o0 = 0.0f, o1 = 0.0f;
        const float* vb = v_sh + j * KSTR;
        const float* pw = p_sh + w * WIN;
#pragma unroll 8
        for (int t = 0; t < WIN; t++) {
            float pp = pw[t];
            o0 += pp * vb[t * KSTR + lane];
            o1 += pp * vb[t * KSTR + lane + 32];
        }
        size_t ob = (size_t)(q0 + j) * HD + (size_t)h * HDIM;
        __nv_bfloat16 h0 = __float2bfloat16(o0);
        __nv_bfloat16 h1 = __float2bfloat16(o1);
        g_ahi[ob + lane]      = h0;
        g_ahi[ob + lane + 32] = h1;
        g_alo[ob + lane]      = __float2bfloat16(o0 - __bfloat162float(h0));
        g_alo[ob + lane + 32] = __float2bfloat16(o1 - __bfloat162float(h1));
        __syncwarp();
    }
}

// ---------------- Launch ----------------
extern "C" void kernel_launch(void* const* d_in, const int* in_sizes, int n_in,
                              void* d_out, int out_size) {
    (void)in_sizes; (void)n_in; (void)out_size;
    const float* x     = (const float*)d_in[0];
    const int*   pos   = (const int*)  d_in[1];
    const float* Wq    = (const float*)d_in[2];
    const float* bq    = (const float*)d_in[3];
    const float* Wk    = (const float*)d_in[4];
    const float* bk    = (const float*)d_in[5];
    const float* Wv    = (const float*)d_in[6];
    const float* bv    = (const float*)d_in[7];
    const float* Wo    = (const float*)d_in[8];
    const float* bo    = (const float*)d_in[9];
    const float* sinks = (const float*)d_in[10];
    float* out = (float*)d_out;

    __nv_bfloat16 *xhi, *xlo, *wqh, *wql, *wkh, *wkl, *wvh, *wvl, *woh, *wol;
    cudaGetSymbolAddress((void**)&xhi, g_xhi);  cudaGetSymbolAddress((void**)&xlo, g_xlo);
    cudaGetSymbolAddress((void**)&wqh, g_Wqhi); cudaGetSymbolAddress((void**)&wql, g_Wqlo);
    cudaGetSymbolAddress((void**)&wkh, g_Wkhi); cudaGetSymbolAddress((void**)&wkl, g_Wklo);
    cudaGetSymbolAddress((void**)&wvh, g_Wvhi); cudaGetSymbolAddress((void**)&wvl, g_Wvlo);
    cudaGetSymbolAddress((void**)&woh, g_Wohi); cudaGetSymbolAddress((void**)&wol, g_Wolo);

    size_t asz = (size_t)(2 * NKEY * KSTR + QT * 512 + 8 * WIN) * sizeof(float);
    cudaFuncSetAttribute(qkv_gemm,   cudaFuncAttributeMaxDynamicSharedMemorySize, GSMEM);
    cudaFuncSetAttribute(oproj_gemm, cudaFuncAttributeMaxDynamicSharedMemorySize, GSMEM);
    cudaFuncSetAttribute(attn_kernel, cudaFuncAttributeMaxDynamicSharedMemorySize, (int)asz);

    // pre-split fp32 -> bf16 hi/lo
    auto blocks = [](int n) { return (n / 4 + 255) / 256; };
    split_kernel<<<blocks(SEQ*EMB), 256>>>(x,  xhi, xlo, SEQ*EMB,  SEQ*EMB);
    split_kernel<<<blocks(HD*EMB),  256>>>(Wq, wqh, wql, HD*EMB,   HD*EMB);
    split_kernel<<<blocks(KVD*EMB), 256>>>(Wk, wkh, wkl, KVD*EMB,  KVD*EMB);
    split_kernel<<<blocks(KVD*EMB), 256>>>(Wv, wvh, wvl, KVD*EMB,  KVD*EMB);
    split_kernel<<<blocks(NPAD*HD), 256>>>(Wo, woh, wol, EMB*HD,   NPAD*HD);

    qkv_gemm<<<dim3(40, 8), 256, GSMEM>>>(bq, bk, bv);
    rope_kernel<<<SEQ, 256>>>(pos);
    attn_kernel<<<dim3(NKV, SEQ / QT), 256, asz>>>(sinks);
    oproj_gemm<<<dim3(23, 8), 256, GSMEM>>>(bo, out);
}